// round 1
// baseline (speedup 1.0000x reference)
#include <cuda_runtime.h>
#include <cstdint>
#include <math.h>

#define B_TOTAL 32768
#define NSLOT   5
#define D_IN    512
#define DK      16
#define NV      7           // 2 read vectors + 5 write vectors
#define TB      512         // batches per block (kernel 1)
#define DCH     8           // d-chunk per stage
#define NCHUNK  (D_IN / DCH)
#define TROW    (TB + 4)    // padded transposed-tile row
#define SMEM_FLOATS (D_IN*DK + 2*DCH*TROW)
#define SMEM_BYTES  (SMEM_FLOATS * 4)

// projection scratch: P[v][b][k]; v: 0,1 = read slots 0,1; 2..6 = write slots 0..4
__device__ float g_P[NV][B_TOTAL][DK];

// ---------------------------------------------------------------------------
// Kernel 1: block-diagonal projection  P[v][b][:] = src[b, slot, :] @ W_v
// grid = (B/TB, 7), 128 threads. 8x8 register tile per thread.
// ---------------------------------------------------------------------------
__global__ __launch_bounds__(128) void proj_kernel(
    const float* __restrict__ q, const float* __restrict__ kk,
    const float* __restrict__ wr, const float* __restrict__ ww)
{
    extern __shared__ float sh[];
    float* sW    = sh;                 // [512][16]
    float* tiles = sh + D_IN * DK;     // [2][DCH][TROW] transposed input tile

    const int v = blockIdx.y;
    const float* src; const float* W; int slot;
    if (v < 2) { src = q;  slot = v;     W = wr + (size_t)v * D_IN * DK; }
    else       { src = kk; slot = v - 2; W = ww + (size_t)(v - 2) * D_IN * DK; }
    const int b0  = blockIdx.x * TB;
    const int tid = threadIdx.x;

    // stage W into smem (8192 floats)
    {
        const float4* Ws = (const float4*)W;
        float4*       Wd = (float4*)sW;
        #pragma unroll
        for (int i = 0; i < 16; i++) Wd[tid + i * 128] = Ws[tid + i * 128];
    }

    // each thread stages 4 batch-rows (8 floats of d each) per chunk
    const float* srow[4];
    #pragma unroll
    for (int j = 0; j < 4; j++) {
        int bl = tid + j * 128;
        srow[j] = src + ((size_t)(b0 + bl) * NSLOT + slot) * D_IN;
    }

    // stage chunk 0 into buffer 0 (transposed: tile[dd][batch])
    {
        float* tb = tiles;
        #pragma unroll
        for (int j = 0; j < 4; j++) {
            int bl = tid + j * 128;
            float4 a = *(const float4*)(srow[j] + 0);
            float4 b = *(const float4*)(srow[j] + 4);
            tb[0*TROW + bl] = a.x; tb[1*TROW + bl] = a.y;
            tb[2*TROW + bl] = a.z; tb[3*TROW + bl] = a.w;
            tb[4*TROW + bl] = b.x; tb[5*TROW + bl] = b.y;
            tb[6*TROW + bl] = b.z; tb[7*TROW + bl] = b.w;
        }
    }
    __syncthreads();

    const int kg = tid & 1;        // 2 k-groups of 8
    const int bg = tid >> 1;       // 64 batch-groups of 8
    const int k0 = kg * 8;
    const int bb = bg * 8;

    float acc[8][8];
    #pragma unroll
    for (int i = 0; i < 8; i++)
        #pragma unroll
        for (int j = 0; j < 8; j++) acc[i][j] = 0.0f;

    float4 pf[8];
    for (int c = 0; c < NCHUNK; c++) {
        // prefetch next chunk into registers
        if (c < NCHUNK - 1) {
            const int d0n = (c + 1) * DCH;
            #pragma unroll
            for (int j = 0; j < 4; j++) {
                pf[2*j]     = *(const float4*)(srow[j] + d0n);
                pf[2*j + 1] = *(const float4*)(srow[j] + d0n + 4);
            }
        }
        // compute current chunk
        const float* tb = tiles + (c & 1) * (DCH * TROW);
        #pragma unroll
        for (int dd = 0; dd < DCH; dd++) {
            float4 qa = *(const float4*)(tb + dd * TROW + bb);
            float4 qb = *(const float4*)(tb + dd * TROW + bb + 4);
            const float* wrow = sW + (c * DCH + dd) * DK + k0;
            float4 wa = *(const float4*)(wrow);
            float4 wb = *(const float4*)(wrow + 4);
            float qv[8] = {qa.x, qa.y, qa.z, qa.w, qb.x, qb.y, qb.z, qb.w};
            float wv[8] = {wa.x, wa.y, wa.z, wa.w, wb.x, wb.y, wb.z, wb.w};
            #pragma unroll
            for (int i = 0; i < 8; i++)
                #pragma unroll
                for (int j = 0; j < 8; j++)
                    acc[i][j] = fmaf(qv[i], wv[j], acc[i][j]);
        }
        // store prefetched chunk into the other buffer
        if (c < NCHUNK - 1) {
            float* tb2 = tiles + ((c + 1) & 1) * (DCH * TROW);
            #pragma unroll
            for (int j = 0; j < 4; j++) {
                int bl = tid + j * 128;
                tb2[0*TROW + bl] = pf[2*j].x;     tb2[1*TROW + bl] = pf[2*j].y;
                tb2[2*TROW + bl] = pf[2*j].z;     tb2[3*TROW + bl] = pf[2*j].w;
                tb2[4*TROW + bl] = pf[2*j + 1].x; tb2[5*TROW + bl] = pf[2*j + 1].y;
                tb2[6*TROW + bl] = pf[2*j + 1].z; tb2[7*TROW + bl] = pf[2*j + 1].w;
            }
        }
        __syncthreads();
    }

    #pragma unroll
    for (int i = 0; i < 8; i++) {
        float* dst = &g_P[v][b0 + bb + i][k0];
        *(float4*)(dst)     = make_float4(acc[i][0], acc[i][1], acc[i][2], acc[i][3]);
        *(float4*)(dst + 4) = make_float4(acc[i][4], acc[i][5], acc[i][6], acc[i][7]);
    }
}

// ---------------------------------------------------------------------------
// Kernel 2: scores + threefry gumbel + argmax -> one-hot outputs
// ---------------------------------------------------------------------------
__device__ __forceinline__ uint32_t rotl32(uint32_t x, int r) {
    return (x << r) | (x >> (32 - r));
}

// JAX threefry2x32 with key (0, key), counter (0, ctr); partitionable path
// returns x0 ^ x1 for 32-bit bits.
__device__ __forceinline__ uint32_t threefry_bits(uint32_t key, uint32_t ctr)
{
    const uint32_t ks0 = 0u, ks1 = key, ks2 = 0x1BD11BDAu ^ key;
    uint32_t x0 = ks0;          // c0 (hi) = 0, + ks0
    uint32_t x1 = ctr + ks1;    // c1 (lo) = ctr, + ks1
#define R4(a,b,cc,d)                                   \
    x0 += x1; x1 = rotl32(x1,(a));  x1 ^= x0;          \
    x0 += x1; x1 = rotl32(x1,(b));  x1 ^= x0;          \
    x0 += x1; x1 = rotl32(x1,(cc)); x1 ^= x0;          \
    x0 += x1; x1 = rotl32(x1,(d));  x1 ^= x0;
    R4(13,15,26,6);   x0 += ks1; x1 += ks2 + 1u;
    R4(17,29,16,24);  x0 += ks2; x1 += ks0 + 2u;
    R4(13,15,26,6);   x0 += ks0; x1 += ks1 + 3u;
    R4(17,29,16,24);  x0 += ks1; x1 += ks2 + 4u;
    R4(13,15,26,6);   x0 += ks2; x1 += ks0 + 5u;
#undef R4
    return x0 ^ x1;
}

__device__ __forceinline__ float gumbel_from_bits(uint32_t bits)
{
    // JAX uniform: ((bits>>9)|0x3f800000) as float - 1, then *(1-minval)+minval, max(minval,.)
    float u = __uint_as_float((bits >> 9) | 0x3f800000u) - 1.0f;
    float val = fmaxf(1e-10f, u * (1.0f - 1e-10f) + 1e-10f);
    return -logf(-logf(val));
}

__global__ __launch_bounds__(256) void score_kernel(float* __restrict__ out)
{
    const int b = blockIdx.x * blockDim.x + threadIdx.x;
    if (b >= B_TOTAL) return;

    float r0[DK], r1[DK];
    #pragma unroll
    for (int t = 0; t < 4; t++) {
        ((float4*)r0)[t] = ((const float4*)&g_P[0][b][0])[t];
        ((float4*)r1)[t] = ((const float4*)&g_P[1][b][0])[t];
    }

    float z0[NSLOT], z1[NSLOT];
    #pragma unroll
    for (int m = 0; m < NSLOT; m++) {
        float wv[DK];
        #pragma unroll
        for (int t = 0; t < 4; t++)
            ((float4*)wv)[t] = ((const float4*)&g_P[2 + m][b][0])[t];

        float s0 = 0.0f, s1 = 0.0f;
        #pragma unroll
        for (int t = 0; t < DK; t++) {
            s0 = fmaf(r0[t], wv[t], s0);
            s1 = fmaf(r1[t], wv[t], s1);
        }
        s0 *= 0.25f;  // / sqrt(16), exact
        s1 *= 0.25f;

        const uint32_t ctr = (uint32_t)(b * NSLOT + m);
        z0[m] = s0 + gumbel_from_bits(threefry_bits(42u, ctr));
        z1[m] = s1 + gumbel_from_bits(threefry_bits(43u, ctr));
    }

    int a0 = 0, a1 = 0;
    float b0v = z0[0], b1v = z1[0];
    #pragma unroll
    for (int m = 1; m < NSLOT; m++) {
        if (z0[m] > b0v) { b0v = z0[m]; a0 = m; }
        if (z1[m] > b1v) { b1v = z1[m]; a1 = m; }
    }

    float* o1 = out + (size_t)b * NSLOT;
    float* o2 = out + (size_t)B_TOTAL * NSLOT + (size_t)b * NSLOT;
    #pragma unroll
    for (int m = 0; m < NSLOT; m++) {
        o1[m] = (m == a0) ? 1.0f : 0.0f;   // y_hard: non-arg entries are exactly 0,
        o2[m] = (m == a1) ? 1.0f : 0.0f;   // arg entry within ~1ulp of 1 in reference
    }
}

// ---------------------------------------------------------------------------
extern "C" void kernel_launch(void* const* d_in, const int* in_sizes, int n_in,
                              void* d_out, int out_size)
{
    const float* q  = (const float*)d_in[0];
    const float* kk = (const float*)d_in[1];
    const float* wr = (const float*)d_in[2];
    const float* ww = (const float*)d_in[3];
    float* out = (float*)d_out;

    cudaFuncSetAttribute(proj_kernel,
                         cudaFuncAttributeMaxDynamicSharedMemorySize, SMEM_BYTES);

    dim3 grid1(B_TOTAL / TB, NV);
    proj_kernel<<<grid1, 128, SMEM_BYTES>>>(q, kk, wr, ww);

    score_kernel<<<B_TOTAL / 256, 256>>>(out);
}

// round 3
// speedup vs baseline: 1.2691x; 1.2691x over previous
#include <cuda_runtime.h>
#include <cstdint>
#include <math.h>

#define B_TOTAL 32768
#define NSLOT   5
#define D_IN    512
#define DK      16
#define NV      7
#define TB      512                 // batches per block
#define DSUP    16                  // d-values per staging superstep
#define NSTEP   (D_IN / DSUP)       // 32
#define TROW    516                 // padded transposed-tile row (16B-aligned, LDS conflict-free)
#define SM_W    (D_IN * DK)         // 8192 floats
#define SM_TILE (DSUP * TROW)       // 8256 floats
#define SMEM_FLOATS (SM_W + 2 * SM_TILE)
#define SMEM_BYTES  (SMEM_FLOATS * 4)   // 98816 B

typedef unsigned long long ull;

// projection scratch: P[v][b][k]; v: 0,1 = read slots 0,1; 2..6 = write slots 0..4
__device__ float g_P[NV][B_TOTAL][DK];

__device__ __forceinline__ void fma2(ull& d, ull a, ull b) {
    asm("fma.rn.f32x2 %0, %1, %2, %0;" : "+l"(d) : "l"(a), "l"(b));
}
__device__ __forceinline__ ull pack2(float x) {
    ull r; asm("mov.b64 %0, {%1, %1};" : "=l"(r) : "f"(x)); return r;
}
__device__ __forceinline__ void unpack2(ull a, float& lo, float& hi) {
    asm("mov.b64 {%0, %1}, %2;" : "=f"(lo), "=f"(hi) : "l"(a));
}

// ---------------------------------------------------------------------------
// Kernel 1: block-diagonal projection with FFMA2 + coalesced staging
// grid = (64, 7), 128 threads.
// ---------------------------------------------------------------------------
__global__ __launch_bounds__(128) void proj_kernel(
    const float* __restrict__ q, const float* __restrict__ kk,
    const float* __restrict__ wr, const float* __restrict__ ww)
{
    extern __shared__ float sh[];
    float* sW    = sh;            // [512][16]
    float* tiles = sh + SM_W;     // [2][DSUP][TROW], transposed: tile[d_local][batch]

    const int v = blockIdx.y;
    const float* src; const float* W; int slot;
    if (v < 2) { src = q;  slot = v;     W = wr + (size_t)v * D_IN * DK; }
    else       { src = kk; slot = v - 2; W = ww + (size_t)(v - 2) * D_IN * DK; }
    const int b0  = blockIdx.x * TB;
    const int tid = threadIdx.x;
    const int lan = tid & 31;
    const int wrp = tid >> 5;

    // stage W into smem (8192 floats)
    {
        const float4* Ws = (const float4*)W;
        float4*       Wd = (float4*)sW;
        #pragma unroll
        for (int i = 0; i < 16; i++) Wd[tid + i * 128] = Ws[tid + i * 128];
    }

    // Coalesced staging geometry: within a warp, 4 lanes cover 64B of one row.
    //   lane -> row offset (lan>>2), 16B-chunk (lan&3). Row J (0..15): rbase + J*8.
    const int rbase = wrp * 128 + (lan >> 2);
    const int c4    = lan & 3;
    const float* gbase = src + (size_t)(b0 + rbase) * (NSLOT * D_IN)
                             + (size_t)slot * D_IN + c4 * 4;
    const size_t rowstride = (size_t)8 * NSLOT * D_IN;   // 8 batch-rows per J step

    float4 pf[8];

    // ---- stage step 0 into buffer 0 ----
    #pragma unroll
    for (int half = 0; half < 2; half++) {
        #pragma unroll
        for (int j2 = 0; j2 < 8; j2++)
            pf[j2] = *(const float4*)(gbase + (size_t)(half * 8 + j2) * rowstride);
        #pragma unroll
        for (int j2 = 0; j2 < 8; j2++) {
            int r = rbase + (half * 8 + j2) * 8;
            tiles[(c4 * 4 + 0) * TROW + r] = pf[j2].x;
            tiles[(c4 * 4 + 1) * TROW + r] = pf[j2].y;
            tiles[(c4 * 4 + 2) * TROW + r] = pf[j2].z;
            tiles[(c4 * 4 + 3) * TROW + r] = pf[j2].w;
        }
    }
    __syncthreads();

    const int kg = tid & 1;        // 2 k-groups of 8
    const int bg = tid >> 1;       // 64 batch-groups of 8
    const int k0 = kg * 8;
    const int bb = bg * 8;

    ull acc[4][8];                 // [batch-pair][k]  (pairs along batch)
    #pragma unroll
    for (int p = 0; p < 4; p++)
        #pragma unroll
        for (int j = 0; j < 8; j++) acc[p][j] = 0ull;

    for (int s = 0; s < NSTEP; s++) {
        float* tb = tiles + (s & 1) * SM_TILE;
        float* tn = tiles + ((s + 1) & 1) * SM_TILE;
        const bool more = (s + 1) < NSTEP;
        const int d0n = (s + 1) * DSUP;

        // prefetch half A of next step
        if (more) {
            #pragma unroll
            for (int j2 = 0; j2 < 8; j2++)
                pf[j2] = *(const float4*)(gbase + (size_t)j2 * rowstride + d0n);
        }

        // compute dd = 0..7
        #pragma unroll
        for (int dd = 0; dd < 8; dd++) {
            const ulonglong2* qp = (const ulonglong2*)(tb + dd * TROW + bb);
            ulonglong2 qa = qp[0], qb = qp[1];           // batches bb..bb+7 as 4 pairs
            const float4* wrow = (const float4*)(sW + (s * DSUP + dd) * DK + k0);
            float4 wa = wrow[0], wb = wrow[1];
            ull wp[8] = { pack2(wa.x), pack2(wa.y), pack2(wa.z), pack2(wa.w),
                          pack2(wb.x), pack2(wb.y), pack2(wb.z), pack2(wb.w) };
            #pragma unroll
            for (int j = 0; j < 8; j++) {
                fma2(acc[0][j], qa.x, wp[j]);
                fma2(acc[1][j], qa.y, wp[j]);
                fma2(acc[2][j], qb.x, wp[j]);
                fma2(acc[3][j], qb.y, wp[j]);
            }
        }

        if (more) {
            // store half A of next step, then prefetch half B
            #pragma unroll
            for (int j2 = 0; j2 < 8; j2++) {
                int r = rbase + j2 * 8;
                tn[(c4 * 4 + 0) * TROW + r] = pf[j2].x;
                tn[(c4 * 4 + 1) * TROW + r] = pf[j2].y;
                tn[(c4 * 4 + 2) * TROW + r] = pf[j2].z;
                tn[(c4 * 4 + 3) * TROW + r] = pf[j2].w;
            }
            #pragma unroll
            for (int j2 = 0; j2 < 8; j2++)
                pf[j2] = *(const float4*)(gbase + (size_t)(8 + j2) * rowstride + d0n);
        }

        // compute dd = 8..15
        #pragma unroll
        for (int dd = 8; dd < 16; dd++) {
            const ulonglong2* qp = (const ulonglong2*)(tb + dd * TROW + bb);
            ulonglong2 qa = qp[0], qb = qp[1];
            const float4* wrow = (const float4*)(sW + (s * DSUP + dd) * DK + k0);
            float4 wa = wrow[0], wb = wrow[1];
            ull wp[8] = { pack2(wa.x), pack2(wa.y), pack2(wa.z), pack2(wa.w),
                          pack2(wb.x), pack2(wb.y), pack2(wb.z), pack2(wb.w) };
            #pragma unroll
            for (int j = 0; j < 8; j++) {
                fma2(acc[0][j], qa.x, wp[j]);
                fma2(acc[1][j], qa.y, wp[j]);
                fma2(acc[2][j], qb.x, wp[j]);
                fma2(acc[3][j], qb.y, wp[j]);
            }
        }

        if (more) {
            #pragma unroll
            for (int j2 = 0; j2 < 8; j2++) {
                int r = rbase + (8 + j2) * 8;
                tn[(c4 * 4 + 0) * TROW + r] = pf[j2].x;
                tn[(c4 * 4 + 1) * TROW + r] = pf[j2].y;
                tn[(c4 * 4 + 2) * TROW + r] = pf[j2].z;
                tn[(c4 * 4 + 3) * TROW + r] = pf[j2].w;
            }
            __syncthreads();
        }
    }

    // write results: batch-pair p holds batches (bb+2p, bb+2p+1)
    #pragma unroll
    for (int p = 0; p < 4; p++) {
        float lo[8], hi[8];
        #pragma unroll
        for (int j = 0; j < 8; j++) unpack2(acc[p][j], lo[j], hi[j]);
        float* d0 = &g_P[v][b0 + bb + 2 * p][k0];
        float* d1 = &g_P[v][b0 + bb + 2 * p + 1][k0];
        *(float4*)(d0)     = make_float4(lo[0], lo[1], lo[2], lo[3]);
        *(float4*)(d0 + 4) = make_float4(lo[4], lo[5], lo[6], lo[7]);
        *(float4*)(d1)     = make_float4(hi[0], hi[1], hi[2], hi[3]);
        *(float4*)(d1 + 4) = make_float4(hi[4], hi[5], hi[6], hi[7]);
    }
}

// ---------------------------------------------------------------------------
// Kernel 2: scores + threefry gumbel + argmax -> one-hot outputs
// ---------------------------------------------------------------------------
__device__ __forceinline__ uint32_t rotl32(uint32_t x, int r) {
    return (x << r) | (x >> (32 - r));
}

__device__ __forceinline__ uint32_t threefry_bits(uint32_t key, uint32_t ctr)
{
    const uint32_t ks0 = 0u, ks1 = key, ks2 = 0x1BD11BDAu ^ key;
    uint32_t x0 = ks0;
    uint32_t x1 = ctr + ks1;
#define R4(a,b,cc,d)                                   \
    x0 += x1; x1 = rotl32(x1,(a));  x1 ^= x0;          \
    x0 += x1; x1 = rotl32(x1,(b));  x1 ^= x0;          \
    x0 += x1; x1 = rotl32(x1,(cc)); x1 ^= x0;          \
    x0 += x1; x1 = rotl32(x1,(d));  x1 ^= x0;
    R4(13,15,26,6);   x0 += ks1; x1 += ks2 + 1u;
    R4(17,29,16,24);  x0 += ks2; x1 += ks0 + 2u;
    R4(13,15,26,6);   x0 += ks0; x1 += ks1 + 3u;
    R4(17,29,16,24);  x0 += ks1; x1 += ks2 + 4u;
    R4(13,15,26,6);   x0 += ks2; x1 += ks0 + 5u;
#undef R4
    return x0 ^ x1;
}

__device__ __forceinline__ float gumbel_from_bits(uint32_t bits)
{
    float u = __uint_as_float((bits >> 9) | 0x3f800000u) - 1.0f;
    float val = fmaxf(1e-10f, u * (1.0f - 1e-10f) + 1e-10f);
    return -logf(-logf(val));
}

__global__ __launch_bounds__(128) void score_kernel(float* __restrict__ out)
{
    const int b = blockIdx.x * blockDim.x + threadIdx.x;
    if (b >= B_TOTAL) return;

    float r0[DK], r1[DK];
    #pragma unroll
    for (int t = 0; t < 4; t++) {
        ((float4*)r0)[t] = ((const float4*)&g_P[0][b][0])[t];
        ((float4*)r1)[t] = ((const float4*)&g_P[1][b][0])[t];
    }

    float z0[NSLOT], z1[NSLOT];
    #pragma unroll
    for (int m = 0; m < NSLOT; m++) {
        float wv[DK];
        #pragma unroll
        for (int t = 0; t < 4; t++)
            ((float4*)wv)[t] = ((const float4*)&g_P[2 + m][b][0])[t];

        float s0 = 0.0f, s1 = 0.0f;
        #pragma unroll
        for (int t = 0; t < DK; t++) {
            s0 = fmaf(r0[t], wv[t], s0);
            s1 = fmaf(r1[t], wv[t], s1);
        }
        s0 *= 0.25f;
        s1 *= 0.25f;

        const uint32_t ctr = (uint32_t)(b * NSLOT + m);
        z0[m] = s0 + gumbel_from_bits(threefry_bits(42u, ctr));
        z1[m] = s1 + gumbel_from_bits(threefry_bits(43u, ctr));
    }

    int a0 = 0, a1 = 0;
    float b0v = z0[0], b1v = z1[0];
    #pragma unroll
    for (int m = 1; m < NSLOT; m++) {
        if (z0[m] > b0v) { b0v = z0[m]; a0 = m; }
        if (z1[m] > b1v) { b1v = z1[m]; a1 = m; }
    }

    float* o1 = out + (size_t)b * NSLOT;
    float* o2 = out + (size_t)B_TOTAL * NSLOT + (size_t)b * NSLOT;
    #pragma unroll
    for (int m = 0; m < NSLOT; m++) {
        o1[m] = (m == a0) ? 1.0f : 0.0f;
        o2[m] = (m == a1) ? 1.0f : 0.0f;
    }
}

// ---------------------------------------------------------------------------
extern "C" void kernel_launch(void* const* d_in, const int* in_sizes, int n_in,
                              void* d_out, int out_size)
{
    const float* q  = (const float*)d_in[0];
    const float* kk = (const float*)d_in[1];
    const float* wr = (const float*)d_in[2];
    const float* ww = (const float*)d_in[3];
    float* out = (float*)d_out;

    cudaFuncSetAttribute(proj_kernel,
                         cudaFuncAttributeMaxDynamicSharedMemorySize, SMEM_BYTES);

    dim3 grid1(B_TOTAL / TB, NV);
    proj_kernel<<<grid1, 128, SMEM_BYTES>>>(q, kk, wr, ww);

    score_kernel<<<B_TOTAL / 128, 128>>>(out);
}